// round 4
// baseline (speedup 1.0000x reference)
#include <cuda_runtime.h>
#include <cuda_bf16.h>
#include <cstdint>
#include <cstring>

// ---------------------------------------------------------------------------
// CLOPLayer: out[b,c,j] = x[b,c,perm[j]], perm = fixed JAX threefry(42)
// neighbor-swap permutation (host-computed bit-exactly, shipped as 28KB
// __grid_constant__ param, unpacked to __device__ global).
// Gather kernel: cp.async double-buffered row pipeline. Row r+1 streams
// GMEM->SMEM (LDGSTS.cg, bypassing L1) while row r is scattered from SMEM
// (stride-1 conflict-free LDS) to coalesced streaming stores. One wave:
// 576 CTAs = 4/SM x 144 SMs worth, 8 rows per CTA, 4608 rows exact.
// ---------------------------------------------------------------------------

#define N_ELEM 7056            // 84*84
#define DIM    84
#define NVEC   (N_ELEM / 4)    // 1764
#define NTHR   512
#define COLS_PER_THR 14        // 7056/512 (exact-ish; bounds checked)
#define VECS_PER_THR 4         // ceil(1764/512)
#define ROWS_PER_BLK 8

__device__ int g_perm[N_ELEM];

struct PermArg { int v[N_ELEM]; };

__global__ void clop_unpack_kernel(const __grid_constant__ PermArg p) {
    int t = blockIdx.x * blockDim.x + threadIdx.x;   // int4 index
    if (t < NVEC) {
        const int4* src = reinterpret_cast<const int4*>(p.v);
        reinterpret_cast<int4*>(g_perm)[t] = src[t];
    }
}

__device__ __forceinline__ void cp_async16(uint32_t saddr, const void* g) {
    asm volatile("cp.async.cg.shared.global [%0], [%1], 16;\n"
                 :: "r"(saddr), "l"(g) : "memory");
}
__device__ __forceinline__ void cp_commit() {
    asm volatile("cp.async.commit_group;\n" ::: "memory");
}
template <int N>
__device__ __forceinline__ void cp_wait() {
    asm volatile("cp.async.wait_group %0;\n" :: "n"(N) : "memory");
}

__device__ __forceinline__ void load_row_async(
    float* buf, uint32_t buf_saddr, const float* __restrict__ xrow, int t)
{
    #pragma unroll
    for (int k = 0; k < VECS_PER_THR; ++k) {
        int v = t + k * NTHR;
        if (v < NVEC) {
            cp_async16(buf_saddr + (uint32_t)v * 16u,
                       reinterpret_cast<const float4*>(xrow) + v);
        }
    }
    cp_commit();
}

extern __shared__ float s_buf[];   // 2 * N_ELEM floats = 56448 B

__global__ __launch_bounds__(NTHR) void clop_gather_kernel(
    const float* __restrict__ x, float* __restrict__ out, int nrows)
{
    const int t = threadIdx.x;
    const int r0 = blockIdx.x * ROWS_PER_BLK;

    float* buf0 = s_buf;
    float* buf1 = s_buf + N_ELEM;
    uint32_t sa0, sa1;
    asm("{ .reg .u64 a; cvta.to.shared.u64 a, %1; cvt.u32.u64 %0, a; }"
        : "=r"(sa0) : "l"(buf0));
    sa1 = sa0 + N_ELEM * 4u;

    // perm values for this thread's columns, in registers for all rows
    int pc[COLS_PER_THR];
    #pragma unroll
    for (int k = 0; k < COLS_PER_THR; ++k) {
        int col = t + k * NTHR;
        pc[k] = (col < N_ELEM) ? g_perm[col] : 0;
    }

    // prologue: start loading row r0 into buf0
    if (r0 < nrows)
        load_row_async(buf0, sa0, x + (size_t)r0 * N_ELEM, t);

    #pragma unroll
    for (int r = 0; r < ROWS_PER_BLK; ++r) {
        int row = r0 + r;
        if (row >= nrows) break;

        float* cur = (r & 1) ? buf1 : buf0;

        // issue next row's loads into the other buffer, then wait for current
        int nrow = row + 1;
        if (r + 1 < ROWS_PER_BLK && nrow < nrows) {
            float*  nb = (r & 1) ? buf0 : buf1;
            uint32_t na = (r & 1) ? sa0 : sa1;
            load_row_async(nb, na, x + (size_t)nrow * N_ELEM, t);
            cp_wait<1>();     // current row's group complete; next may fly
        } else {
            cp_wait<0>();
        }
        __syncthreads();

        // permuted read from smem (stride-1 => conflict-free), coalesced
        // streaming scalar stores
        float* dst = out + (size_t)row * N_ELEM;
        #pragma unroll
        for (int k = 0; k < COLS_PER_THR; ++k) {
            int col = t + k * NTHR;
            if (col < N_ELEM) __stcs(dst + col, cur[pc[k]]);
        }
        __syncthreads();  // all reads of 'cur' done before it is refilled
    }
}

// ---------------------------------------------------------------------------
// Host-side bit-exact JAX RNG replication (threefry2x32, partitionable path)
// ---------------------------------------------------------------------------

static inline uint32_t rotl32(uint32_t v, int r) {
    return (v << r) | (v >> (32 - r));
}

static inline void threefry2x32(uint32_t k0, uint32_t k1,
                                uint32_t& x0, uint32_t& x1)
{
    const uint32_t ks0 = k0;
    const uint32_t ks1 = k1;
    const uint32_t ks2 = k0 ^ k1 ^ 0x1BD11BDAu;
    const int ra[4] = {13, 15, 26, 6};
    const int rb[4] = {17, 29, 16, 24};

    x0 += ks0; x1 += ks1;
    for (int i = 0; i < 4; i++) { x0 += x1; x1 = rotl32(x1, ra[i]); x1 ^= x0; }
    x0 += ks1; x1 += ks2 + 1u;
    for (int i = 0; i < 4; i++) { x0 += x1; x1 = rotl32(x1, rb[i]); x1 ^= x0; }
    x0 += ks2; x1 += ks0 + 2u;
    for (int i = 0; i < 4; i++) { x0 += x1; x1 = rotl32(x1, ra[i]); x1 ^= x0; }
    x0 += ks0; x1 += ks1 + 3u;
    for (int i = 0; i < 4; i++) { x0 += x1; x1 = rotl32(x1, rb[i]); x1 ^= x0; }
    x0 += ks1; x1 += ks2 + 4u;
    for (int i = 0; i < 4; i++) { x0 += x1; x1 = rotl32(x1, ra[i]); x1 ^= x0; }
    x0 += ks2; x1 += ks0 + 5u;
}

static inline uint32_t jax_random_bits32(uint32_t k0, uint32_t k1, uint64_t i) {
    uint32_t x0 = (uint32_t)(i >> 32);
    uint32_t x1 = (uint32_t)(i & 0xFFFFFFFFu);
    threefry2x32(k0, k1, x0, x1);
    return x0 ^ x1;
}

static void compute_perm(int* perm) {
    const int n = N_ELEM;
    const int dim = DIM;
    const int steps = 2 * n - 1;   // 14111

    float probs[5];
    probs[0] = (float)(1.0 - 0.9 / 2.0);
    for (int q = 1; q < 5; q++) probs[q] = (float)(0.9 / 8.0);
    float pc[5];
    pc[0] = probs[0];
    for (int q = 1; q < 5; q++) pc[q] = pc[q - 1] + probs[q];

    const int offsets[5] = {0, 1, -1, dim, -dim};

    for (int t = 0; t < n; t++) perm[t] = t;

    const uint32_t k0 = 0u, k1 = 42u;   // jax.random.key(42)

    for (int s = 0; s < steps; s++) {
        int i = s - (n - 1);
        if (i < 0) i = -i;

        uint32_t bits = jax_random_bits32(k0, k1, (uint64_t)s);
        uint32_t fb = (bits >> 9) | 0x3F800000u;
        float u;
        memcpy(&u, &fb, 4);
        u -= 1.0f;

        float rv = pc[4] * (1.0f - u);
        int ind = 0;
        while (ind < 5 && pc[ind] < rv) ind++;
        if (ind > 4) ind = 4;

        int idx = i + offsets[ind];
        if (ind != 0 && idx > 0 && idx < n) {
            int a = perm[i];
            perm[i] = perm[idx];
            perm[idx] = a;
        }
    }
}

// ---------------------------------------------------------------------------

extern "C" void kernel_launch(void* const* d_in, const int* in_sizes, int n_in,
                              void* d_out, int out_size) {
    const float* x = (const float*)d_in[0];
    float* out = (float*)d_out;
    int total = in_sizes[0];
    int nrows = total / N_ELEM;    // 512*9 = 4608

    static PermArg parg;           // storage only; recomputed every call
    compute_perm(parg.v);

    const int smem_bytes = 2 * N_ELEM * (int)sizeof(float);   // 56448
    static int attr_done = 0;
    if (!attr_done) {
        cudaFuncSetAttribute(clop_gather_kernel,
                             cudaFuncAttributeMaxDynamicSharedMemorySize,
                             smem_bytes);
        attr_done = 1;
    }

    clop_unpack_kernel<<<(NVEC + 255) / 256, 256>>>(parg);

    int nblk = (nrows + ROWS_PER_BLK - 1) / ROWS_PER_BLK;   // 576
    clop_gather_kernel<<<nblk, NTHR, smem_bytes>>>(x, out, nrows);
}